// round 9
// baseline (speedup 1.0000x reference)
#include <cuda_runtime.h>
#include <cuda_bf16.h>
#include <math.h>
#include <cstdint>

#define Nn 8192
#define Dd 64

// ---------------- device scratch ----------------
__device__ __nv_bfloat16 g_zmp_bf[Nn * Dd];
__device__ __nv_bfloat16 g_zsc_bf[Nn * Dd];
__device__ unsigned g_bits[(size_t)Nn * Nn / 32];   // pos bitmask, 8 MB
__device__ float    g_acc[8][Nn];                   // (A,B) for 4 terms
__device__ double   g_loss;

__device__ __forceinline__ unsigned smem_u32(const void* p) {
    unsigned a;
    asm("{ .reg .u64 t; cvta.to.shared.u64 t, %1; cvt.u32.u64 %0, t; }" : "=r"(a) : "l"(p));
    return a;
}
__device__ __forceinline__ float ex2(float x) {   // 2^x, 1 MUFU
    float r; asm("ex2.approx.f32 %0, %1;" : "=f"(r) : "f"(x)); return r;
}
__device__ __forceinline__ unsigned cvt2(float hi, float lo) {  // {hi,lo} -> bf16x2
    unsigned r; asm("cvt.rn.bf16x2.f32 %0, %1, %2;" : "=r"(r) : "f"(hi), "f"(lo)); return r;
}
#define EXPC 2.8853900817779268f   // 2*log2(e): exp(2v) = 2^(v*EXPC)
#define ONE2 0x3F803F80u           // bf16x2 {1.0, 1.0}

#define LDSM_X4(r0, r1, r2, r3, addr) \
    asm volatile("ldmatrix.sync.aligned.m8n8.x4.shared.b16 {%0,%1,%2,%3}, [%4];" \
                 : "=r"(r0), "=r"(r1), "=r"(r2), "=r"(r3) : "r"(addr))

#define MMA_BF16(c, a0, a1, a2, a3, b0, b1) \
    asm volatile("mma.sync.aligned.m16n8k16.row.col.f32.bf16.bf16.f32 " \
                 "{%0,%1,%2,%3}, {%4,%5,%6,%7}, {%8,%9}, {%0,%1,%2,%3};" \
                 : "+f"((c)[0]), "+f"((c)[1]), "+f"((c)[2]), "+f"((c)[3]) \
                 : "r"(a0), "r"(a1), "r"(a2), "r"(a3), "r"(b0), "r"(b1))

#define CP16(dst, src) \
    asm volatile("cp.async.cg.shared.global [%0], [%1], 16;" :: "r"(dst), "l"(src))
#define CP_COMMIT() asm volatile("cp.async.commit_group;" ::: "memory")
#define CP_WAIT0()  asm volatile("cp.async.wait_group 0;" ::: "memory")

// ---------------- kernel 1: normalize both inputs + zero accumulators ----------------
// grid (1024, 2): y selects input; blocks x<256 of y==0 also zero g_acc.
__global__ void normalize_kernel(const float* __restrict__ zmp,
                                 const float* __restrict__ zsc) {
    const float* z = blockIdx.y ? zsc : zmp;
    __nv_bfloat16* out = blockIdx.y ? g_zsc_bf : g_zmp_bf;
    if (blockIdx.y == 0 && blockIdx.x < 256) {
        ((float*)g_acc)[blockIdx.x * 256 + threadIdx.x] = 0.0f;
        if (blockIdx.x == 0 && threadIdx.x == 0) g_loss = 0.0;
    }
    int row  = blockIdx.x * 8 + (threadIdx.x >> 5);
    int lane = threadIdx.x & 31;
    float2 v = ((const float2*)(z + (size_t)row * Dd))[lane];
    float s = v.x * v.x + v.y * v.y;
    #pragma unroll
    for (int o = 16; o; o >>= 1) s += __shfl_xor_sync(0xffffffffu, s, o);
    float inv = 1.0f / fmaxf(sqrtf(s), 1e-12f);
    __nv_bfloat162 h = __floats2bfloat162_rn(v.x * inv, v.y * inv);
    ((__nv_bfloat162*)(out + (size_t)row * Dd))[lane] = h;
}

// ---------------- kernel 2: pack pos into bitmask (8 front-batched loads) ----------------
#define PK_8 (Nn * (size_t)Nn / 32)        // float4s per eighth
__global__ void pack_pos_kernel(const float4* __restrict__ pos4) {
    unsigned base = blockIdx.x * blockDim.x + threadIdx.x;
    unsigned lane = threadIdx.x & 31;
    float4 v[8];
    #pragma unroll
    for (int h = 0; h < 8; h++) v[h] = pos4[base + (size_t)h * PK_8];
    #pragma unroll
    for (int h = 0; h < 8; h++) {
        unsigned nib = (v[h].x != 0.f ? 1u : 0u) | (v[h].y != 0.f ? 2u : 0u) |
                       (v[h].z != 0.f ? 4u : 0u) | (v[h].w != 0.f ? 8u : 0u);
        unsigned word = nib << (4 * (lane & 7));
        word |= __shfl_xor_sync(0xffffffffu, word, 1);
        word |= __shfl_xor_sync(0xffffffffu, word, 2);
        word |= __shfl_xor_sync(0xffffffffu, word, 4);
        if ((lane & 7) == 0) g_bits[(base + (size_t)h * PK_8) >> 3] = word;
    }
}

// ---------------- kernel 3: HMMA similarity + MMA-reduced epilogue ----------------
// grid (64, 64, 4); mode: 0=(mp,sc) 1=(sc,mp) 2=(mp,mp) 3=(sc,sc). 128x128 tile/CTA.
#define A_OFF    0
#define B_OFF    16384
#define BITS_OFF 32768      // 128 rows x uint4
#define SMEM_SZ  34816

__global__ __launch_bounds__(256, 3) void sim_mma_kernel() {
    __shared__ __align__(128) unsigned char sm[SMEM_SZ];
    const unsigned smb = smem_u32(sm);

    const int mode = blockIdx.z;
    const __nv_bfloat16* Ap = (mode == 1 || mode == 3) ? g_zsc_bf : g_zmp_bf;
    const __nv_bfloat16* Bp = (mode == 0 || mode == 3) ? g_zsc_bf : g_zmp_bf;
    const int bi = blockIdx.y, bj = blockIdx.x;
    const int tid = threadIdx.x, lane = tid & 31, w = tid >> 5;

    // ---- stage tiles (swizzled) via cp.async ----
    const char* Ag = (const char*)(Ap + (size_t)bi * 128 * Dd);
    const char* Bg = (const char*)(Bp + (size_t)bj * 128 * Dd);
    #pragma unroll
    for (int i = 0; i < 4; i++) {
        int seg = i * 256 + tid;
        int row = seg >> 3, c = seg & 7;
        unsigned off = row * 128 + ((c ^ (row & 7)) << 4);
        CP16(smb + A_OFF + off, Ag + row * 128 + c * 16);
        CP16(smb + B_OFF + off, Bg + row * 128 + c * 16);
    }
    if (tid < 128)
        CP16(smb + BITS_OFF + tid * 16,
             (const char*)(g_bits + (size_t)(bi * 128 + tid) * 256 + bj * 4));
    CP_COMMIT();
    CP_WAIT0();
    __syncthreads();

    // ---- A fragments for all 4 k-steps (held in regs) ----
    const int rA = w * 16 + (lane & 15);
    const int cA_sel = lane >> 4;
    const unsigned aBase = smb + A_OFF + rA * 128;
    unsigned a[4][4];
    #pragma unroll
    for (int ks = 0; ks < 4; ks++) {
        unsigned ca = 2 * ks + cA_sel;
        LDSM_X4(a[ks][0], a[ks][1], a[ks][2], a[ks][3], aBase + ((ca ^ (rA & 7)) << 4));
    }

    const int nB = (lane & 7) + ((lane >> 4) & 1) * 8;
    const int cB_sel = (lane >> 3) & 1;
    const int qr = lane >> 2, qc = lane & 3;
    const int r_lo = w * 16 + qr, r_hi = r_lo + 8;

    // persistent reduction accumulators: Cs = row sums, Cp = masked row sums
    float Cs[4] = {0.f, 0.f, 0.f, 0.f}, Cp[4] = {0.f, 0.f, 0.f, 0.f};

    #pragma unroll
    for (int nb = 0; nb < 4; nb++) {
        float acc[4][4];
        #pragma unroll
        for (int u = 0; u < 4; u++)
            #pragma unroll
            for (int j = 0; j < 4; j++) acc[u][j] = 0.f;

        #pragma unroll
        for (int ks = 0; ks < 4; ks++) {
            unsigned cb = 2 * ks + cB_sel;
            #pragma unroll
            for (int g = 0; g < 2; g++) {
                int col = nb * 32 + g * 16 + nB;
                unsigned b0, b1, b2, b3;
                LDSM_X4(b0, b1, b2, b3, smb + B_OFF + col * 128 + ((cb ^ (col & 7)) << 4));
                MMA_BF16(acc[2 * g + 0], a[ks][0], a[ks][1], a[ks][2], a[ks][3], b0, b1);
                MMA_BF16(acc[2 * g + 1], a[ks][0], a[ks][1], a[ks][2], a[ks][3], b2, b3);
            }
        }

        // bits for this 32-col block
        unsigned bl, bh;
        asm volatile("ld.shared.b32 %0, [%1];" : "=r"(bl) : "r"(smb + BITS_OFF + r_lo * 16 + nb * 4));
        asm volatile("ld.shared.b32 %0, [%1];" : "=r"(bh) : "r"(smb + BITS_OFF + r_hi * 16 + nb * 4));

        // exp + mask, then reduce via MMA against all-ones B
        float e[4][4], m[4][4];
        #pragma unroll
        for (int u = 0; u < 4; u++) {
            const int sb = u * 8 + qc * 2;
            e[u][0] = ex2(acc[u][0] * EXPC);
            e[u][1] = ex2(acc[u][1] * EXPC);
            e[u][2] = ex2(acc[u][2] * EXPC);
            e[u][3] = ex2(acc[u][3] * EXPC);
            unsigned l = bl >> sb, h = bh >> sb;
            m[u][0] = (l & 1u) ? e[u][0] : 0.f;
            m[u][1] = (l & 2u) ? e[u][1] : 0.f;
            m[u][2] = (h & 1u) ? e[u][2] : 0.f;
            m[u][3] = (h & 2u) ? e[u][3] : 0.f;
        }
        #pragma unroll
        for (int g = 0; g < 2; g++) {
            const int u0 = 2 * g, u1 = 2 * g + 1;
            unsigned sa0 = cvt2(e[u0][1], e[u0][0]);
            unsigned sa1 = cvt2(e[u0][3], e[u0][2]);
            unsigned sa2 = cvt2(e[u1][1], e[u1][0]);
            unsigned sa3 = cvt2(e[u1][3], e[u1][2]);
            MMA_BF16(Cs, sa0, sa1, sa2, sa3, ONE2, ONE2);
            unsigned pa0 = cvt2(m[u0][1], m[u0][0]);
            unsigned pa1 = cvt2(m[u0][3], m[u0][2]);
            unsigned pa2 = cvt2(m[u1][1], m[u1][0]);
            unsigned pa3 = cvt2(m[u1][3], m[u1][2]);
            MMA_BF16(Cp, pa0, pa1, pa2, pa3, ONE2, ONE2);
        }
    }

    // Cs[0]/Cp[0] = row r_lo sums; Cs[2]/Cp[2] = row r_hi sums (all qc identical)
    if (qc == 0) {
        atomicAdd(&g_acc[2 * mode + 0][bi * 128 + r_lo], Cs[0]);
        atomicAdd(&g_acc[2 * mode + 1][bi * 128 + r_lo], Cp[0]);
        atomicAdd(&g_acc[2 * mode + 0][bi * 128 + r_hi], Cs[2]);
        atomicAdd(&g_acc[2 * mode + 1][bi * 128 + r_hi], Cp[2]);
    }
}

// ---------------- kernel 4a: parallel partial finalize ----------------
__global__ void finalize_part_kernel() {
    __shared__ double sred[128];
    int i = blockIdx.x * 128 + threadIdx.x;
    double local = 0.0;
    #pragma unroll
    for (int t = 0; t < 4; t++) {
        double A = (double)g_acc[2 * t][i];
        double B = (double)g_acc[2 * t + 1][i];
        local += log(B) - log(A + 1e-8);
    }
    sred[threadIdx.x] = local;
    __syncthreads();
    for (int o = 64; o; o >>= 1) {
        if (threadIdx.x < o) sred[threadIdx.x] += sred[threadIdx.x + o];
        __syncthreads();
    }
    if (threadIdx.x == 0) atomicAdd(&g_loss, sred[0]);
}

// ---------------- kernel 4b: emit scalar ----------------
__global__ void finalize_out_kernel(float* out) {
    out[0] = (float)(-g_loss / (double)Nn);
}

// ---------------- launch ----------------
extern "C" void kernel_launch(void* const* d_in, const int* in_sizes, int n_in,
                              void* d_out, int out_size) {
    const float* z_mp = (const float*)d_in[0];
    const float* z_sc = (const float*)d_in[1];
    const float* pos  = (const float*)d_in[2];
    float* out = (float*)d_out;

    dim3 ng(Nn / 8, 2);
    normalize_kernel<<<ng, 256>>>(z_mp, z_sc);
    pack_pos_kernel<<<8192, 256>>>((const float4*)pos);
    dim3 g(Nn / 128, Nn / 128, 4);
    sim_mma_kernel<<<g, 256>>>();
    finalize_part_kernel<<<64, 128>>>();
    finalize_out_kernel<<<1, 1>>>(out);
}

// round 11
// speedup vs baseline: 1.0885x; 1.0885x over previous
#include <cuda_runtime.h>
#include <cuda_bf16.h>
#include <math.h>
#include <cstdint>

#define Nn 8192
#define Dd 64

// ---------------- device scratch ----------------
__device__ __nv_bfloat16 g_zmp_bf[Nn * Dd];
__device__ __nv_bfloat16 g_zsc_bf[Nn * Dd];
__device__ unsigned g_bits[(size_t)Nn * Nn / 32];   // pos bitmask, 8 MB
__device__ float    g_acc[8][Nn];                   // (A,B) for 4 terms
__device__ double   g_loss;
__device__ unsigned g_cnt;

__device__ __forceinline__ unsigned smem_u32(const void* p) {
    unsigned a;
    asm("{ .reg .u64 t; cvta.to.shared.u64 t, %1; cvt.u32.u64 %0, t; }" : "=r"(a) : "l"(p));
    return a;
}
__device__ __forceinline__ float ex2(float x) {   // 2^x, 1 MUFU
    float r; asm("ex2.approx.f32 %0, %1;" : "=f"(r) : "f"(x)); return r;
}
#define EXPC 2.8853900817779268f   // 2*log2(e): exp(2v) = 2^(v*EXPC)

#define LDSM_X4(r0, r1, r2, r3, addr) \
    asm volatile("ldmatrix.sync.aligned.m8n8.x4.shared.b16 {%0,%1,%2,%3}, [%4];" \
                 : "=r"(r0), "=r"(r1), "=r"(r2), "=r"(r3) : "r"(addr))

#define MMA_BF16(c, a0, a1, a2, a3, b0, b1) \
    asm volatile("mma.sync.aligned.m16n8k16.row.col.f32.bf16.bf16.f32 " \
                 "{%0,%1,%2,%3}, {%4,%5,%6,%7}, {%8,%9}, {%0,%1,%2,%3};" \
                 : "+f"((c)[0]), "+f"((c)[1]), "+f"((c)[2]), "+f"((c)[3]) \
                 : "r"(a0), "r"(a1), "r"(a2), "r"(a3), "r"(b0), "r"(b1))

#define CP16(dst, src) \
    asm volatile("cp.async.cg.shared.global [%0], [%1], 16;" :: "r"(dst), "l"(src))
#define CP_COMMIT() asm volatile("cp.async.commit_group;" ::: "memory")
#define CP_WAIT0()  asm volatile("cp.async.wait_group 0;" ::: "memory")

// ---------------- kernel 1: row L2-normalize -> bf16 (+ zero acc on first) ----------------
__global__ void normalize_kernel(const float* __restrict__ z, int which) {
    __nv_bfloat16* out = which ? g_zsc_bf : g_zmp_bf;
    if (which == 0 && blockIdx.x < 256) {
        ((float*)g_acc)[blockIdx.x * 256 + threadIdx.x] = 0.0f;
        if (blockIdx.x == 0 && threadIdx.x == 0) { g_loss = 0.0; g_cnt = 0u; }
    }
    int row  = blockIdx.x * 8 + (threadIdx.x >> 5);
    int lane = threadIdx.x & 31;
    float2 v = ((const float2*)(z + (size_t)row * Dd))[lane];
    float s = v.x * v.x + v.y * v.y;
    #pragma unroll
    for (int o = 16; o; o >>= 1) s += __shfl_xor_sync(0xffffffffu, s, o);
    float inv = 1.0f / fmaxf(sqrtf(s), 1e-12f);
    __nv_bfloat162 h = __floats2bfloat162_rn(v.x * inv, v.y * inv);
    ((__nv_bfloat162*)(out + (size_t)row * Dd))[lane] = h;
}

// ---------------- kernel 2: pack pos into bitmask (8 front-batched loads) ----------------
#define PK_8 (Nn * (size_t)Nn / 32)        // float4s per eighth
__global__ void pack_pos_kernel(const float4* __restrict__ pos4) {
    unsigned base = blockIdx.x * blockDim.x + threadIdx.x;
    unsigned lane = threadIdx.x & 31;
    float4 v[8];
    #pragma unroll
    for (int h = 0; h < 8; h++) v[h] = pos4[base + (size_t)h * PK_8];
    #pragma unroll
    for (int h = 0; h < 8; h++) {
        unsigned nib = (v[h].x != 0.f ? 1u : 0u) | (v[h].y != 0.f ? 2u : 0u) |
                       (v[h].z != 0.f ? 4u : 0u) | (v[h].w != 0.f ? 8u : 0u);
        unsigned word = nib << (4 * (lane & 7));
        word |= __shfl_xor_sync(0xffffffffu, word, 1);
        word |= __shfl_xor_sync(0xffffffffu, word, 2);
        word |= __shfl_xor_sync(0xffffffffu, word, 4);
        if ((lane & 7) == 0) g_bits[(base + (size_t)h * PK_8) >> 3] = word;
    }
}

// ---------------- kernel 3: HMMA similarity, 128x256 tile/CTA ----------------
// grid (32, 64, 4); mode: 0=(mp,sc) 1=(sc,mp) 2=(mp,mp) 3=(sc,sc).
// dynamic smem 56KB: A 16KB @0, B 32KB @16384, bits 8KB @49152.
#define A_OFF    0
#define B_OFF    16384
#define BITS_OFF 49152
#define DYN_SZ   57344

__global__ __launch_bounds__(256, 3) void sim_mma_kernel() {
    extern __shared__ __align__(128) unsigned char sm[];
    const unsigned smb = smem_u32(sm);
    const unsigned sbb = smb + BITS_OFF;

    const int mode = blockIdx.z;
    const __nv_bfloat16* Ap = (mode == 1 || mode == 3) ? g_zsc_bf : g_zmp_bf;
    const __nv_bfloat16* Bp = (mode == 0 || mode == 3) ? g_zsc_bf : g_zmp_bf;
    const int bi = blockIdx.y, bj = blockIdx.x;       // rows bi*128, cols bj*256
    const int tid = threadIdx.x, lane = tid & 31, w = tid >> 5;

    // ---- stage tiles (swizzled) via cp.async ----
    const char* Ag = (const char*)(Ap + (size_t)bi * 128 * Dd);
    const char* Bg = (const char*)(Bp + (size_t)bj * 256 * Dd);
    #pragma unroll
    for (int i = 0; i < 4; i++) {
        int seg = i * 256 + tid;                 // A: 1024 segs of 16B
        int row = seg >> 3, c = seg & 7;
        unsigned off = row * 128 + ((c ^ (row & 7)) << 4);
        CP16(smb + A_OFF + off, Ag + row * 128 + c * 16);
    }
    #pragma unroll
    for (int i = 0; i < 8; i++) {
        int seg = i * 256 + tid;                 // B: 2048 segs of 16B
        int row = seg >> 3, c = seg & 7;
        unsigned off = row * 128 + ((c ^ (row & 7)) << 4);
        CP16(smb + B_OFF + off, Bg + row * 128 + c * 16);
    }
    {   // bits: row = tid>>1, half = tid&1  (128 rows x 8 words)
        int row = tid >> 1, half = tid & 1;
        CP16(sbb + tid * 16,
             (const char*)(g_bits + (size_t)(bi * 128 + row) * 256 + bj * 8 + half * 4));
    }
    CP_COMMIT();
    CP_WAIT0();
    __syncthreads();

    // ---- A fragments for all 4 k-steps (held in regs) ----
    const int rA = w * 16 + (lane & 15);
    const int cA_sel = lane >> 4;
    const unsigned aBase = smb + A_OFF + rA * 128;
    unsigned a[4][4];
    #pragma unroll
    for (int ks = 0; ks < 4; ks++) {
        unsigned ca = 2 * ks + cA_sel;
        LDSM_X4(a[ks][0], a[ks][1], a[ks][2], a[ks][3], aBase + ((ca ^ (rA & 7)) << 4));
    }

    const int nB = (lane & 7) + ((lane >> 4) & 1) * 8;
    const int cB_sel = (lane >> 3) & 1;
    const int qr = lane >> 2, qc = lane & 3;
    const int r_lo = w * 16 + qr, r_hi = r_lo + 8;

    float s_lo = 0.f, p_lo = 0.f, s_hi = 0.f, p_hi = 0.f;

    #pragma unroll
    for (int nb = 0; nb < 8; nb++) {
        float acc[4][4];
        #pragma unroll
        for (int u = 0; u < 4; u++)
            #pragma unroll
            for (int j = 0; j < 4; j++) acc[u][j] = 0.f;

        #pragma unroll
        for (int ks = 0; ks < 4; ks++) {
            unsigned cb = 2 * ks + cB_sel;
            #pragma unroll
            for (int g = 0; g < 2; g++) {
                int col = nb * 32 + g * 16 + nB;
                unsigned b0, b1, b2, b3;
                LDSM_X4(b0, b1, b2, b3, smb + B_OFF + col * 128 + ((cb ^ (col & 7)) << 4));
                MMA_BF16(acc[2 * g + 0], a[ks][0], a[ks][1], a[ks][2], a[ks][3], b0, b1);
                MMA_BF16(acc[2 * g + 1], a[ks][0], a[ks][1], a[ks][2], a[ks][3], b2, b3);
            }
        }

        unsigned bl, bh;
        asm volatile("ld.shared.b32 %0, [%1];" : "=r"(bl) : "r"(sbb + (r_lo * 8 + nb) * 4));
        asm volatile("ld.shared.b32 %0, [%1];" : "=r"(bh) : "r"(sbb + (r_hi * 8 + nb) * 4));

        #pragma unroll
        for (int u = 0; u < 4; u++) {
            const int sb = u * 8 + qc * 2;
            float e0 = ex2(acc[u][0] * EXPC);
            float e1 = ex2(acc[u][1] * EXPC);
            float e2 = ex2(acc[u][2] * EXPC);
            float e3 = ex2(acc[u][3] * EXPC);
            unsigned l = bl >> sb, h = bh >> sb;
            s_lo += e0 + e1;
            s_hi += e2 + e3;
            p_lo += ((l & 1u) ? e0 : 0.f) + ((l & 2u) ? e1 : 0.f);
            p_hi += ((h & 1u) ? e2 : 0.f) + ((h & 2u) ? e3 : 0.f);
        }
    }

    #pragma unroll
    for (int o = 1; o <= 2; o <<= 1) {
        s_lo += __shfl_xor_sync(0xffffffffu, s_lo, o);
        p_lo += __shfl_xor_sync(0xffffffffu, p_lo, o);
        s_hi += __shfl_xor_sync(0xffffffffu, s_hi, o);
        p_hi += __shfl_xor_sync(0xffffffffu, p_hi, o);
    }
    if (qc == 0) {
        atomicAdd(&g_acc[2 * mode + 0][bi * 128 + r_lo], s_lo);
        atomicAdd(&g_acc[2 * mode + 1][bi * 128 + r_lo], p_lo);
        atomicAdd(&g_acc[2 * mode + 0][bi * 128 + r_hi], s_hi);
        atomicAdd(&g_acc[2 * mode + 1][bi * 128 + r_hi], p_hi);
    }
}

// ---------------- kernel 4: finalize (single kernel, last block emits) ----------------
__global__ void finalize_kernel(float* out) {
    __shared__ double sred[128];
    int i = blockIdx.x * 128 + threadIdx.x;
    double local = 0.0;
    #pragma unroll
    for (int t = 0; t < 4; t++) {
        double A = (double)g_acc[2 * t][i];
        double B = (double)g_acc[2 * t + 1][i];
        local += log(B) - log(A + 1e-8);
    }
    sred[threadIdx.x] = local;
    __syncthreads();
    for (int o = 64; o; o >>= 1) {
        if (threadIdx.x < o) sred[threadIdx.x] += sred[threadIdx.x + o];
        __syncthreads();
    }
    if (threadIdx.x == 0) {
        atomicAdd(&g_loss, sred[0]);
        __threadfence();
        unsigned old = atomicInc(&g_cnt, 63u);            // wraps to 0 after 64th
        if (old == 63u) {
            double full = atomicAdd(&g_loss, 0.0);
            out[0] = (float)(-full / (double)Nn);
        }
    }
}

// ---------------- launch ----------------
extern "C" void kernel_launch(void* const* d_in, const int* in_sizes, int n_in,
                              void* d_out, int out_size) {
    const float* z_mp = (const float*)d_in[0];
    const float* z_sc = (const float*)d_in[1];
    const float* pos  = (const float*)d_in[2];
    float* out = (float*)d_out;

    // host-side attribute set (not a stream op; graph-capture legal)
    cudaFuncSetAttribute(sim_mma_kernel,
                         cudaFuncAttributeMaxDynamicSharedMemorySize, DYN_SZ);

    normalize_kernel<<<Nn / 8, 256>>>(z_mp, 0);            // launch 0
    normalize_kernel<<<Nn / 8, 256>>>(z_sc, 1);            // launch 1
    pack_pos_kernel<<<8192, 256>>>((const float4*)pos);    // launch 2
    dim3 g(Nn / 256, Nn / 128, 4);
    sim_mma_kernel<<<g, 256, DYN_SZ>>>();                  // launch 3 <- ncu captures this
    finalize_kernel<<<64, 128>>>(out);                     // launch 4
}

// round 12
// speedup vs baseline: 1.2017x; 1.1040x over previous
#include <cuda_runtime.h>
#include <cuda_bf16.h>
#include <math.h>
#include <cstdint>

#define Nn 8192
#define Dd 64

// ---------------- device scratch ----------------
__device__ __nv_bfloat16 g_zmp_bf[Nn * Dd];    // unscaled (B side)
__device__ __nv_bfloat16 g_zsc_bf[Nn * Dd];
__device__ __nv_bfloat16 g_zmp_s[Nn * Dd];     // pre-scaled by EXPC (A side)
__device__ __nv_bfloat16 g_zsc_s[Nn * Dd];
__device__ unsigned g_bits[(size_t)Nn * Nn / 32];   // pos bitmask, 8 MB
__device__ float    g_acc[8][Nn];                   // (A,B) for 4 terms
__device__ double   g_loss;
__device__ unsigned g_cnt;

__device__ __forceinline__ unsigned smem_u32(const void* p) {
    unsigned a;
    asm("{ .reg .u64 t; cvta.to.shared.u64 t, %1; cvt.u32.u64 %0, t; }" : "=r"(a) : "l"(p));
    return a;
}
__device__ __forceinline__ float ex2(float x) {   // 2^x, 1 MUFU
    float r; asm("ex2.approx.f32 %0, %1;" : "=f"(r) : "f"(x)); return r;
}
#define EXPC 2.8853900817779268f   // 2*log2(e): exp(2v) = 2^(v*EXPC)

#define LDSM_X4(r0, r1, r2, r3, addr) \
    asm volatile("ldmatrix.sync.aligned.m8n8.x4.shared.b16 {%0,%1,%2,%3}, [%4];" \
                 : "=r"(r0), "=r"(r1), "=r"(r2), "=r"(r3) : "r"(addr))

#define MMA_BF16(c, a0, a1, a2, a3, b0, b1) \
    asm volatile("mma.sync.aligned.m16n8k16.row.col.f32.bf16.bf16.f32 " \
                 "{%0,%1,%2,%3}, {%4,%5,%6,%7}, {%8,%9}, {%0,%1,%2,%3};" \
                 : "+f"((c)[0]), "+f"((c)[1]), "+f"((c)[2]), "+f"((c)[3]) \
                 : "r"(a0), "r"(a1), "r"(a2), "r"(a3), "r"(b0), "r"(b1))

#define CP16(dst, src) \
    asm volatile("cp.async.cg.shared.global [%0], [%1], 16;" :: "r"(dst), "l"(src))
#define CP_COMMIT() asm volatile("cp.async.commit_group;" ::: "memory")
#define CP_WAIT0()  asm volatile("cp.async.wait_group 0;" ::: "memory")

// ---------------- kernel 1: row L2-normalize -> bf16 x2 (+ zero acc on first) ----------------
__global__ void normalize_kernel(const float* __restrict__ z, int which) {
    __nv_bfloat16* out  = which ? g_zsc_bf : g_zmp_bf;
    __nv_bfloat16* outs = which ? g_zsc_s  : g_zmp_s;
    if (which == 0 && blockIdx.x < 256) {
        ((float*)g_acc)[blockIdx.x * 256 + threadIdx.x] = 0.0f;
        if (blockIdx.x == 0 && threadIdx.x == 0) { g_loss = 0.0; g_cnt = 0u; }
    }
    int row  = blockIdx.x * 8 + (threadIdx.x >> 5);
    int lane = threadIdx.x & 31;
    float2 v = ((const float2*)(z + (size_t)row * Dd))[lane];
    float s = v.x * v.x + v.y * v.y;
    #pragma unroll
    for (int o = 16; o; o >>= 1) s += __shfl_xor_sync(0xffffffffu, s, o);
    float inv = 1.0f / fmaxf(sqrtf(s), 1e-12f);
    float nx = v.x * inv, ny = v.y * inv;
    ((__nv_bfloat162*)(out  + (size_t)row * Dd))[lane] = __floats2bfloat162_rn(nx, ny);
    ((__nv_bfloat162*)(outs + (size_t)row * Dd))[lane] =
        __floats2bfloat162_rn(nx * EXPC, ny * EXPC);
}

// ---------------- kernel 2: pack pos into bitmask (8 front-batched loads) ----------------
#define PK_8 (Nn * (size_t)Nn / 32)        // float4s per eighth
__global__ void pack_pos_kernel(const float4* __restrict__ pos4) {
    unsigned base = blockIdx.x * blockDim.x + threadIdx.x;
    unsigned lane = threadIdx.x & 31;
    float4 v[8];
    #pragma unroll
    for (int h = 0; h < 8; h++) v[h] = pos4[base + (size_t)h * PK_8];
    #pragma unroll
    for (int h = 0; h < 8; h++) {
        unsigned nib = (v[h].x != 0.f ? 1u : 0u) | (v[h].y != 0.f ? 2u : 0u) |
                       (v[h].z != 0.f ? 4u : 0u) | (v[h].w != 0.f ? 8u : 0u);
        unsigned word = nib << (4 * (lane & 7));
        word |= __shfl_xor_sync(0xffffffffu, word, 1);
        word |= __shfl_xor_sync(0xffffffffu, word, 2);
        word |= __shfl_xor_sync(0xffffffffu, word, 4);
        if ((lane & 7) == 0) g_bits[(base + (size_t)h * PK_8) >> 3] = word;
    }
}

// ---------------- kernel 3: HMMA similarity, 128x256 tile/CTA ----------------
// grid (32, 64, 4); mode: 0=(mp,sc) 1=(sc,mp) 2=(mp,mp) 3=(sc,sc).
// A side loads the EXPC-scaled copy; B side the unscaled copy.
// dynamic smem 56KB: A 16KB @0, B 32KB @16384, bits 8KB @49152.
#define A_OFF    0
#define B_OFF    16384
#define BITS_OFF 49152
#define DYN_SZ   57344

__global__ __launch_bounds__(256, 3) void sim_mma_kernel() {
    extern __shared__ __align__(128) unsigned char sm[];
    const unsigned smb = smem_u32(sm);
    const unsigned sbb = smb + BITS_OFF;

    const int mode = blockIdx.z;
    const __nv_bfloat16* Ap = (mode == 1 || mode == 3) ? g_zsc_s  : g_zmp_s;
    const __nv_bfloat16* Bp = (mode == 0 || mode == 3) ? g_zsc_bf : g_zmp_bf;
    const int bi = blockIdx.y, bj = blockIdx.x;       // rows bi*128, cols bj*256
    const int tid = threadIdx.x, lane = tid & 31, w = tid >> 5;

    // ---- stage tiles (swizzled) via cp.async ----
    const char* Ag = (const char*)(Ap + (size_t)bi * 128 * Dd);
    const char* Bg = (const char*)(Bp + (size_t)bj * 256 * Dd);
    #pragma unroll
    for (int i = 0; i < 4; i++) {
        int seg = i * 256 + tid;                 // A: 1024 segs of 16B
        int row = seg >> 3, c = seg & 7;
        unsigned off = row * 128 + ((c ^ (row & 7)) << 4);
        CP16(smb + A_OFF + off, Ag + row * 128 + c * 16);
    }
    #pragma unroll
    for (int i = 0; i < 8; i++) {
        int seg = i * 256 + tid;                 // B: 2048 segs of 16B
        int row = seg >> 3, c = seg & 7;
        unsigned off = row * 128 + ((c ^ (row & 7)) << 4);
        CP16(smb + B_OFF + off, Bg + row * 128 + c * 16);
    }
    {   // bits: row = tid>>1, half = tid&1  (128 rows x 8 words)
        int row = tid >> 1, half = tid & 1;
        CP16(sbb + tid * 16,
             (const char*)(g_bits + (size_t)(bi * 128 + row) * 256 + bj * 8 + half * 4));
    }
    CP_COMMIT();
    CP_WAIT0();
    __syncthreads();

    // ---- A fragments for all 4 k-steps (held in regs) ----
    const int rA = w * 16 + (lane & 15);
    const int cA_sel = lane >> 4;
    const unsigned aBase = smb + A_OFF + rA * 128;
    unsigned a[4][4];
    #pragma unroll
    for (int ks = 0; ks < 4; ks++) {
        unsigned ca = 2 * ks + cA_sel;
        LDSM_X4(a[ks][0], a[ks][1], a[ks][2], a[ks][3], aBase + ((ca ^ (rA & 7)) << 4));
    }

    const int nB = (lane & 7) + ((lane >> 4) & 1) * 8;
    const int cB_sel = (lane >> 3) & 1;
    const int qr = lane >> 2, qc = lane & 3;
    const int r_lo = w * 16 + qr, r_hi = r_lo + 8;
    const int qc2 = qc * 2;

    float s_lo = 0.f, p_lo = 0.f, s_hi = 0.f, p_hi = 0.f;

    #pragma unroll
    for (int nb = 0; nb < 8; nb++) {
        float acc[4][4];
        #pragma unroll
        for (int u = 0; u < 4; u++)
            #pragma unroll
            for (int j = 0; j < 4; j++) acc[u][j] = 0.f;

        #pragma unroll
        for (int ks = 0; ks < 4; ks++) {
            unsigned cb = 2 * ks + cB_sel;
            #pragma unroll
            for (int g = 0; g < 2; g++) {
                int col = nb * 32 + g * 16 + nB;
                unsigned b0, b1, b2, b3;
                LDSM_X4(b0, b1, b2, b3, smb + B_OFF + col * 128 + ((cb ^ (col & 7)) << 4));
                MMA_BF16(acc[2 * g + 0], a[ks][0], a[ks][1], a[ks][2], a[ks][3], b0, b1);
                MMA_BF16(acc[2 * g + 1], a[ks][0], a[ks][1], a[ks][2], a[ks][3], b2, b3);
            }
        }

        unsigned bl, bh;
        asm volatile("ld.shared.b32 %0, [%1];" : "=r"(bl) : "r"(sbb + (r_lo * 8 + nb) * 4));
        asm volatile("ld.shared.b32 %0, [%1];" : "=r"(bh) : "r"(sbb + (r_hi * 8 + nb) * 4));
        const unsigned blq = bl >> qc2, bhq = bh >> qc2;   // one shift per word per nb

        #pragma unroll
        for (int u = 0; u < 4; u++) {
            // MMA already produced s*EXPC (A pre-scaled): exp = ex2(acc)
            float e0 = ex2(acc[u][0]);
            float e1 = ex2(acc[u][1]);
            float e2 = ex2(acc[u][2]);
            float e3 = ex2(acc[u][3]);
            s_lo += e0 + e1;
            s_hi += e2 + e3;
            // immediate-mask bit tests (LOP3 -> predicate, FSEL)
            p_lo += ((blq & (1u << (u * 8))) ? e0 : 0.f)
                  + ((blq & (2u << (u * 8))) ? e1 : 0.f);
            p_hi += ((bhq & (1u << (u * 8))) ? e2 : 0.f)
                  + ((bhq & (2u << (u * 8))) ? e3 : 0.f);
        }
    }

    #pragma unroll
    for (int o = 1; o <= 2; o <<= 1) {
        s_lo += __shfl_xor_sync(0xffffffffu, s_lo, o);
        p_lo += __shfl_xor_sync(0xffffffffu, p_lo, o);
        s_hi += __shfl_xor_sync(0xffffffffu, s_hi, o);
        p_hi += __shfl_xor_sync(0xffffffffu, p_hi, o);
    }
    if (qc == 0) {
        atomicAdd(&g_acc[2 * mode + 0][bi * 128 + r_lo], s_lo);
        atomicAdd(&g_acc[2 * mode + 1][bi * 128 + r_lo], p_lo);
        atomicAdd(&g_acc[2 * mode + 0][bi * 128 + r_hi], s_hi);
        atomicAdd(&g_acc[2 * mode + 1][bi * 128 + r_hi], p_hi);
    }
}

// ---------------- kernel 4: finalize (single kernel, last block emits) ----------------
__global__ void finalize_kernel(float* out) {
    __shared__ double sred[128];
    int i = blockIdx.x * 128 + threadIdx.x;
    double local = 0.0;
    #pragma unroll
    for (int t = 0; t < 4; t++) {
        double A = (double)g_acc[2 * t][i];
        double B = (double)g_acc[2 * t + 1][i];
        local += log(B) - log(A + 1e-8);
    }
    sred[threadIdx.x] = local;
    __syncthreads();
    for (int o = 64; o; o >>= 1) {
        if (threadIdx.x < o) sred[threadIdx.x] += sred[threadIdx.x + o];
        __syncthreads();
    }
    if (threadIdx.x == 0) {
        atomicAdd(&g_loss, sred[0]);
        __threadfence();
        unsigned old = atomicInc(&g_cnt, 63u);            // wraps to 0 after 64th
        if (old == 63u) {
            double full = atomicAdd(&g_loss, 0.0);
            out[0] = (float)(-full / (double)Nn);
        }
    }
}

// ---------------- launch ----------------
extern "C" void kernel_launch(void* const* d_in, const int* in_sizes, int n_in,
                              void* d_out, int out_size) {
    const float* z_mp = (const float*)d_in[0];
    const float* z_sc = (const float*)d_in[1];
    const float* pos  = (const float*)d_in[2];
    float* out = (float*)d_out;

    cudaFuncSetAttribute(sim_mma_kernel,
                         cudaFuncAttributeMaxDynamicSharedMemorySize, DYN_SZ);

    normalize_kernel<<<Nn / 8, 256>>>(z_mp, 0);            // launch 0
    normalize_kernel<<<Nn / 8, 256>>>(z_sc, 1);            // launch 1
    pack_pos_kernel<<<8192, 256>>>((const float4*)pos);    // launch 2
    dim3 g(Nn / 256, Nn / 128, 4);
    sim_mma_kernel<<<g, 256, DYN_SZ>>>();                  // launch 3 <- ncu captures this
    finalize_kernel<<<64, 128>>>(out);                     // launch 4
}

// round 13
// speedup vs baseline: 1.3084x; 1.0888x over previous
#include <cuda_runtime.h>
#include <cuda_bf16.h>
#include <math.h>
#include <cstdint>

#define Nn 8192
#define Dd 64

// ---------------- device scratch ----------------
__device__ __nv_bfloat16 g_zmp_bf[Nn * Dd];    // unscaled (B side)
__device__ __nv_bfloat16 g_zsc_bf[Nn * Dd];
__device__ __nv_bfloat16 g_zmp_s[Nn * Dd];     // pre-scaled by EXPC (A side)
__device__ __nv_bfloat16 g_zsc_s[Nn * Dd];
__device__ unsigned g_bits[(size_t)Nn * Nn / 32];   // pos bitmask, 8 MB
__device__ float    g_acc[8][Nn];                   // (A,B) for 4 terms
__device__ double   g_loss;
__device__ unsigned g_cnt;

__device__ __forceinline__ unsigned smem_u32(const void* p) {
    unsigned a;
    asm("{ .reg .u64 t; cvta.to.shared.u64 t, %1; cvt.u32.u64 %0, t; }" : "=r"(a) : "l"(p));
    return a;
}
__device__ __forceinline__ float ex2(float x) {   // 2^x, 1 MUFU
    float r; asm("ex2.approx.f32 %0, %1;" : "=f"(r) : "f"(x)); return r;
}
#define EXPC 2.8853900817779268f   // 2*log2(e): exp(2v) = 2^(v*EXPC)

#define LDSM_X4(r0, r1, r2, r3, addr) \
    asm volatile("ldmatrix.sync.aligned.m8n8.x4.shared.b16 {%0,%1,%2,%3}, [%4];" \
                 : "=r"(r0), "=r"(r1), "=r"(r2), "=r"(r3) : "r"(addr))

#define MMA_BF16(c, a0, a1, a2, a3, b0, b1) \
    asm volatile("mma.sync.aligned.m16n8k16.row.col.f32.bf16.bf16.f32 " \
                 "{%0,%1,%2,%3}, {%4,%5,%6,%7}, {%8,%9}, {%0,%1,%2,%3};" \
                 : "+f"((c)[0]), "+f"((c)[1]), "+f"((c)[2]), "+f"((c)[3]) \
                 : "r"(a0), "r"(a1), "r"(a2), "r"(a3), "r"(b0), "r"(b1))

#define CP16(dst, src) \
    asm volatile("cp.async.cg.shared.global [%0], [%1], 16;" :: "r"(dst), "l"(src))
#define CP_COMMIT() asm volatile("cp.async.commit_group;" ::: "memory")
#define CP_WAIT0()  asm volatile("cp.async.wait_group 0;" ::: "memory")

// ---------------- kernel 1: row L2-normalize -> bf16 x2 (+ zero acc on first) ----------------
__global__ void normalize_kernel(const float* __restrict__ z, int which) {
    __nv_bfloat16* out  = which ? g_zsc_bf : g_zmp_bf;
    __nv_bfloat16* outs = which ? g_zsc_s  : g_zmp_s;
    if (which == 0 && blockIdx.x < 256) {
        ((float*)g_acc)[blockIdx.x * 256 + threadIdx.x] = 0.0f;
        if (blockIdx.x == 0 && threadIdx.x == 0) { g_loss = 0.0; g_cnt = 0u; }
    }
    int row  = blockIdx.x * 8 + (threadIdx.x >> 5);
    int lane = threadIdx.x & 31;
    float2 v = ((const float2*)(z + (size_t)row * Dd))[lane];
    float s = v.x * v.x + v.y * v.y;
    #pragma unroll
    for (int o = 16; o; o >>= 1) s += __shfl_xor_sync(0xffffffffu, s, o);
    float inv = 1.0f / fmaxf(sqrtf(s), 1e-12f);
    float nx = v.x * inv, ny = v.y * inv;
    ((__nv_bfloat162*)(out  + (size_t)row * Dd))[lane] = __floats2bfloat162_rn(nx, ny);
    ((__nv_bfloat162*)(outs + (size_t)row * Dd))[lane] =
        __floats2bfloat162_rn(nx * EXPC, ny * EXPC);
}

// ---------------- kernel 2: pack pos into bitmask (8 front-batched loads) ----------------
#define PK_8 (Nn * (size_t)Nn / 32)        // float4s per eighth
__global__ void pack_pos_kernel(const float4* __restrict__ pos4) {
    unsigned base = blockIdx.x * blockDim.x + threadIdx.x;
    unsigned lane = threadIdx.x & 31;
    float4 v[8];
    #pragma unroll
    for (int h = 0; h < 8; h++) v[h] = pos4[base + (size_t)h * PK_8];
    #pragma unroll
    for (int h = 0; h < 8; h++) {
        unsigned nib = (v[h].x != 0.f ? 1u : 0u) | (v[h].y != 0.f ? 2u : 0u) |
                       (v[h].z != 0.f ? 4u : 0u) | (v[h].w != 0.f ? 8u : 0u);
        unsigned word = nib << (4 * (lane & 7));
        word |= __shfl_xor_sync(0xffffffffu, word, 1);
        word |= __shfl_xor_sync(0xffffffffu, word, 2);
        word |= __shfl_xor_sync(0xffffffffu, word, 4);
        if ((lane & 7) == 0) g_bits[(base + (size_t)h * PK_8) >> 3] = word;
    }
}

// ---------------- kernel 3: HMMA similarity, 128x256 tile/CTA ----------------
// grid (32, 64, 4); mode: 0=(mp,sc) 1=(sc,mp) 2=(mp,mp) 3=(sc,sc).
// A side loads the EXPC-scaled copy; B side the unscaled copy.
// dynamic smem 56KB: A 16KB @0, B 32KB @16384, bits 8KB @49152.
#define A_OFF    0
#define B_OFF    16384
#define BITS_OFF 49152
#define DYN_SZ   57344

__global__ __launch_bounds__(256, 3) void sim_mma_kernel() {
    extern __shared__ __align__(128) unsigned char sm[];
    const unsigned smb = smem_u32(sm);
    const unsigned sbb = smb + BITS_OFF;

    const int mode = blockIdx.z;
    const __nv_bfloat16* Ap = (mode == 1 || mode == 3) ? g_zsc_s  : g_zmp_s;
    const __nv_bfloat16* Bp = (mode == 0 || mode == 3) ? g_zsc_bf : g_zmp_bf;
    const int bi = blockIdx.y, bj = blockIdx.x;       // rows bi*128, cols bj*256
    const int tid = threadIdx.x, lane = tid & 31, w = tid >> 5;

    // ---- stage tiles (swizzled) via cp.async ----
    const char* Ag = (const char*)(Ap + (size_t)bi * 128 * Dd);
    const char* Bg = (const char*)(Bp + (size_t)bj * 256 * Dd);
    #pragma unroll
    for (int i = 0; i < 4; i++) {
        int seg = i * 256 + tid;                 // A: 1024 segs of 16B
        int row = seg >> 3, c = seg & 7;
        unsigned off = row * 128 + ((c ^ (row & 7)) << 4);
        CP16(smb + A_OFF + off, Ag + row * 128 + c * 16);
    }
    #pragma unroll
    for (int i = 0; i < 8; i++) {
        int seg = i * 256 + tid;                 // B: 2048 segs of 16B
        int row = seg >> 3, c = seg & 7;
        unsigned off = row * 128 + ((c ^ (row & 7)) << 4);
        CP16(smb + B_OFF + off, Bg + row * 128 + c * 16);
    }
    {   // bits: row = tid>>1, half = tid&1  (128 rows x 8 words)
        int row = tid >> 1, half = tid & 1;
        CP16(sbb + tid * 16,
             (const char*)(g_bits + (size_t)(bi * 128 + row) * 256 + bj * 8 + half * 4));
    }
    CP_COMMIT();
    CP_WAIT0();
    __syncthreads();

    // ---- A fragments for all 4 k-steps (held in regs) ----
    const int rA = w * 16 + (lane & 15);
    const int cA_sel = lane >> 4;
    const unsigned aBase = smb + A_OFF + rA * 128;
    unsigned a[4][4];
    #pragma unroll
    for (int ks = 0; ks < 4; ks++) {
        unsigned ca = 2 * ks + cA_sel;
        LDSM_X4(a[ks][0], a[ks][1], a[ks][2], a[ks][3], aBase + ((ca ^ (rA & 7)) << 4));
    }

    const int nB = (lane & 7) + ((lane >> 4) & 1) * 8;
    const int cB_sel = (lane >> 3) & 1;
    const int qr = lane >> 2, qc = lane & 3;
    const int r_lo = w * 16 + qr, r_hi = r_lo + 8;
    const int qc2 = qc * 2;

    // induction pointers for the per-nb bits words
    unsigned bAddrLo = sbb + r_lo * 32;   // 8 words per row -> 32 B stride
    unsigned bAddrHi = sbb + r_hi * 32;

    float s_lo = 0.f, p_lo = 0.f, s_hi = 0.f, p_hi = 0.f;

    #pragma unroll
    for (int nb = 0; nb < 8; nb++) {
        float acc[4][4];
        #pragma unroll
        for (int u = 0; u < 4; u++)
            #pragma unroll
            for (int j = 0; j < 4; j++) acc[u][j] = 0.f;

        #pragma unroll
        for (int ks = 0; ks < 4; ks++) {
            unsigned cb = 2 * ks + cB_sel;
            #pragma unroll
            for (int g = 0; g < 2; g++) {
                int col = nb * 32 + g * 16 + nB;
                unsigned b0, b1, b2, b3;
                LDSM_X4(b0, b1, b2, b3, smb + B_OFF + col * 128 + ((cb ^ (col & 7)) << 4));
                MMA_BF16(acc[2 * g + 0], a[ks][0], a[ks][1], a[ks][2], a[ks][3], b0, b1);
                MMA_BF16(acc[2 * g + 1], a[ks][0], a[ks][1], a[ks][2], a[ks][3], b2, b3);
            }
        }

        unsigned bl, bh;
        asm volatile("ld.shared.b32 %0, [%1];" : "=r"(bl) : "r"(bAddrLo + nb * 4));
        asm volatile("ld.shared.b32 %0, [%1];" : "=r"(bh) : "r"(bAddrHi + nb * 4));
        const unsigned blq = bl >> qc2, bhq = bh >> qc2;   // one shift per word per nb

        #pragma unroll
        for (int u = 0; u < 4; u++) {
            // MMA already produced s*EXPC (A pre-scaled): exp = ex2(acc)
            float e0 = ex2(acc[u][0]);
            float e1 = ex2(acc[u][1]);
            float e2 = ex2(acc[u][2]);
            float e3 = ex2(acc[u][3]);
            s_lo += e0 + e1;
            s_hi += e2 + e3;
            // predicated adds: LOP3->pred + @p FADD (no FSEL)
            if (blq & (1u << (u * 8))) p_lo += e0;
            if (blq & (2u << (u * 8))) p_lo += e1;
            if (bhq & (1u << (u * 8))) p_hi += e2;
            if (bhq & (2u << (u * 8))) p_hi += e3;
        }
    }

    #pragma unroll
    for (int o = 1; o <= 2; o <<= 1) {
        s_lo += __shfl_xor_sync(0xffffffffu, s_lo, o);
        p_lo += __shfl_xor_sync(0xffffffffu, p_lo, o);
        s_hi += __shfl_xor_sync(0xffffffffu, s_hi, o);
        p_hi += __shfl_xor_sync(0xffffffffu, p_hi, o);
    }
    if (qc == 0) {
        atomicAdd(&g_acc[2 * mode + 0][bi * 128 + r_lo], s_lo);
        atomicAdd(&g_acc[2 * mode + 1][bi * 128 + r_lo], p_lo);
        atomicAdd(&g_acc[2 * mode + 0][bi * 128 + r_hi], s_hi);
        atomicAdd(&g_acc[2 * mode + 1][bi * 128 + r_hi], p_hi);
    }
}

// ---------------- kernel 4: finalize (single kernel, last block emits) ----------------
__global__ void finalize_kernel(float* out) {
    __shared__ double sred[128];
    int i = blockIdx.x * 128 + threadIdx.x;
    double local = 0.0;
    #pragma unroll
    for (int t = 0; t < 4; t++) {
        double A = (double)g_acc[2 * t][i];
        double B = (double)g_acc[2 * t + 1][i];
        local += log(B) - log(A + 1e-8);
    }
    sred[threadIdx.x] = local;
    __syncthreads();
    for (int o = 64; o; o >>= 1) {
        if (threadIdx.x < o) sred[threadIdx.x] += sred[threadIdx.x + o];
        __syncthreads();
    }
    if (threadIdx.x == 0) {
        atomicAdd(&g_loss, sred[0]);
        __threadfence();
        unsigned old = atomicInc(&g_cnt, 63u);            // wraps to 0 after 64th
        if (old == 63u) {
            double full = atomicAdd(&g_loss, 0.0);
            out[0] = (float)(-full / (double)Nn);
        }
    }
}

// ---------------- launch ----------------
extern "C" void kernel_launch(void* const* d_in, const int* in_sizes, int n_in,
                              void* d_out, int out_size) {
    const float* z_mp = (const float*)d_in[0];
    const float* z_sc = (const float*)d_in[1];
    const float* pos  = (const float*)d_in[2];
    float* out = (float*)d_out;

    cudaFuncSetAttribute(sim_mma_kernel,
                         cudaFuncAttributeMaxDynamicSharedMemorySize, DYN_SZ);

    normalize_kernel<<<Nn / 8, 256>>>(z_mp, 0);            // launch 0
    normalize_kernel<<<Nn / 8, 256>>>(z_sc, 1);            // launch 1
    pack_pos_kernel<<<8192, 256>>>((const float4*)pos);    // launch 2
    dim3 g(Nn / 256, Nn / 128, 4);
    sim_mma_kernel<<<g, 256, DYN_SZ>>>();                  // launch 3 <- ncu captures this
    finalize_kernel<<<64, 128>>>(out);                     // launch 4
}

// round 14
// speedup vs baseline: 1.3182x; 1.0075x over previous
#include <cuda_runtime.h>
#include <cuda_bf16.h>
#include <math.h>
#include <cstdint>

#define Nn 8192
#define Dd 64

// ---------------- device scratch ----------------
__device__ __nv_bfloat16 g_zmp_bf[Nn * Dd];    // unscaled (B side)
__device__ __nv_bfloat16 g_zsc_bf[Nn * Dd];
__device__ __nv_bfloat16 g_zmp_s[Nn * Dd];     // pre-scaled by EXPC (A side)
__device__ __nv_bfloat16 g_zsc_s[Nn * Dd];
__device__ unsigned g_bits[(size_t)Nn * Nn / 32];   // pos bitmask, 8 MB
__device__ float    g_acc[8][Nn];                   // (A,B) for 4 terms
__device__ double   g_loss;
__device__ unsigned g_cnt;

__device__ __forceinline__ unsigned smem_u32(const void* p) {
    unsigned a;
    asm("{ .reg .u64 t; cvta.to.shared.u64 t, %1; cvt.u32.u64 %0, t; }" : "=r"(a) : "l"(p));
    return a;
}
__device__ __forceinline__ float ex2(float x) {   // 2^x, 1 MUFU
    float r; asm("ex2.approx.f32 %0, %1;" : "=f"(r) : "f"(x)); return r;
}
#define EXPC 2.8853900817779268f   // 2*log2(e): exp(2v) = 2^(v*EXPC)

#define LDSM_X4(r0, r1, r2, r3, addr) \
    asm volatile("ldmatrix.sync.aligned.m8n8.x4.shared.b16 {%0,%1,%2,%3}, [%4];" \
                 : "=r"(r0), "=r"(r1), "=r"(r2), "=r"(r3) : "r"(addr))

#define MMA_BF16(c, a0, a1, a2, a3, b0, b1) \
    asm volatile("mma.sync.aligned.m16n8k16.row.col.f32.bf16.bf16.f32 " \
                 "{%0,%1,%2,%3}, {%4,%5,%6,%7}, {%8,%9}, {%0,%1,%2,%3};" \
                 : "+f"((c)[0]), "+f"((c)[1]), "+f"((c)[2]), "+f"((c)[3]) \
                 : "r"(a0), "r"(a1), "r"(a2), "r"(a3), "r"(b0), "r"(b1))

// first k-step: D = A*B + {z,z,z,z}; z==0 lets ptxas use RZ (no per-nb MOV init)
#define MMA_BF16_INIT(c, a0, a1, a2, a3, b0, b1, z) \
    asm volatile("mma.sync.aligned.m16n8k16.row.col.f32.bf16.bf16.f32 " \
                 "{%0,%1,%2,%3}, {%4,%5,%6,%7}, {%8,%9}, {%10,%10,%10,%10};" \
                 : "=f"((c)[0]), "=f"((c)[1]), "=f"((c)[2]), "=f"((c)[3]) \
                 : "r"(a0), "r"(a1), "r"(a2), "r"(a3), "r"(b0), "r"(b1), "f"(z))

#define CP16(dst, src) \
    asm volatile("cp.async.cg.shared.global [%0], [%1], 16;" :: "r"(dst), "l"(src))
#define CP_COMMIT() asm volatile("cp.async.commit_group;" ::: "memory")
#define CP_WAIT0()  asm volatile("cp.async.wait_group 0;" ::: "memory")

// ---------------- kernel 1: row L2-normalize -> bf16 x2 (+ zero acc on first) ----------------
__global__ void normalize_kernel(const float* __restrict__ z, int which) {
    __nv_bfloat16* out  = which ? g_zsc_bf : g_zmp_bf;
    __nv_bfloat16* outs = which ? g_zsc_s  : g_zmp_s;
    if (which == 0 && blockIdx.x < 256) {
        ((float*)g_acc)[blockIdx.x * 256 + threadIdx.x] = 0.0f;
        if (blockIdx.x == 0 && threadIdx.x == 0) { g_loss = 0.0; g_cnt = 0u; }
    }
    int row  = blockIdx.x * 8 + (threadIdx.x >> 5);
    int lane = threadIdx.x & 31;
    float2 v = ((const float2*)(z + (size_t)row * Dd))[lane];
    float s = v.x * v.x + v.y * v.y;
    #pragma unroll
    for (int o = 16; o; o >>= 1) s += __shfl_xor_sync(0xffffffffu, s, o);
    float inv = 1.0f / fmaxf(sqrtf(s), 1e-12f);
    float nx = v.x * inv, ny = v.y * inv;
    ((__nv_bfloat162*)(out  + (size_t)row * Dd))[lane] = __floats2bfloat162_rn(nx, ny);
    ((__nv_bfloat162*)(outs + (size_t)row * Dd))[lane] =
        __floats2bfloat162_rn(nx * EXPC, ny * EXPC);
}

// ---------------- kernel 2: pack pos into bitmask (8 front-batched loads) ----------------
#define PK_8 (Nn * (size_t)Nn / 32)        // float4s per eighth
__global__ void pack_pos_kernel(const float4* __restrict__ pos4) {
    unsigned base = blockIdx.x * blockDim.x + threadIdx.x;
    unsigned lane = threadIdx.x & 31;
    float4 v[8];
    #pragma unroll
    for (int h = 0; h < 8; h++) v[h] = pos4[base + (size_t)h * PK_8];
    #pragma unroll
    for (int h = 0; h < 8; h++) {
        unsigned nib = (v[h].x != 0.f ? 1u : 0u) | (v[h].y != 0.f ? 2u : 0u) |
                       (v[h].z != 0.f ? 4u : 0u) | (v[h].w != 0.f ? 8u : 0u);
        unsigned word = nib << (4 * (lane & 7));
        word |= __shfl_xor_sync(0xffffffffu, word, 1);
        word |= __shfl_xor_sync(0xffffffffu, word, 2);
        word |= __shfl_xor_sync(0xffffffffu, word, 4);
        if ((lane & 7) == 0) g_bits[(base + (size_t)h * PK_8) >> 3] = word;
    }
}

// ---------------- kernel 3: HMMA similarity, 128x256 tile/CTA ----------------
// grid (32, 64, 4); mode: 0=(mp,sc) 1=(sc,mp) 2=(mp,mp) 3=(sc,sc).
// A side loads the EXPC-scaled copy; B side the unscaled copy.
// dynamic smem 56KB: A 16KB @0, B 32KB @16384, bits 8KB @49152.
#define A_OFF    0
#define B_OFF    16384
#define BITS_OFF 49152
#define DYN_SZ   57344

__global__ __launch_bounds__(256, 3) void sim_mma_kernel() {
    extern __shared__ __align__(128) unsigned char sm[];
    const unsigned smb = smem_u32(sm);
    const unsigned sbb = smb + BITS_OFF;

    const int mode = blockIdx.z;
    const __nv_bfloat16* Ap = (mode == 1 || mode == 3) ? g_zsc_s  : g_zmp_s;
    const __nv_bfloat16* Bp = (mode == 0 || mode == 3) ? g_zsc_bf : g_zmp_bf;
    const int bi = blockIdx.y, bj = blockIdx.x;       // rows bi*128, cols bj*256
    const int tid = threadIdx.x, lane = tid & 31, w = tid >> 5;

    // ---- stage tiles (swizzled) via cp.async ----
    const char* Ag = (const char*)(Ap + (size_t)bi * 128 * Dd);
    const char* Bg = (const char*)(Bp + (size_t)bj * 256 * Dd);
    #pragma unroll
    for (int i = 0; i < 4; i++) {
        int seg = i * 256 + tid;                 // A: 1024 segs of 16B
        int row = seg >> 3, c = seg & 7;
        unsigned off = row * 128 + ((c ^ (row & 7)) << 4);
        CP16(smb + A_OFF + off, Ag + row * 128 + c * 16);
    }
    #pragma unroll
    for (int i = 0; i < 8; i++) {
        int seg = i * 256 + tid;                 // B: 2048 segs of 16B
        int row = seg >> 3, c = seg & 7;
        unsigned off = row * 128 + ((c ^ (row & 7)) << 4);
        CP16(smb + B_OFF + off, Bg + row * 128 + c * 16);
    }
    {   // bits: row = tid>>1, half = tid&1  (128 rows x 8 words)
        int row = tid >> 1, half = tid & 1;
        CP16(sbb + tid * 16,
             (const char*)(g_bits + (size_t)(bi * 128 + row) * 256 + bj * 8 + half * 4));
    }
    CP_COMMIT();
    CP_WAIT0();
    __syncthreads();

    // ---- A fragments for all 4 k-steps (held in regs) ----
    const int rA = w * 16 + (lane & 15);
    const int cA_sel = lane >> 4;
    const unsigned aBase = smb + A_OFF + rA * 128;
    unsigned a[4][4];
    #pragma unroll
    for (int ks = 0; ks < 4; ks++) {
        unsigned ca = 2 * ks + cA_sel;
        LDSM_X4(a[ks][0], a[ks][1], a[ks][2], a[ks][3], aBase + ((ca ^ (rA & 7)) << 4));
    }

    const int nB = (lane & 7) + ((lane >> 4) & 1) * 8;
    const int cB_sel = (lane >> 3) & 1;
    const int qr = lane >> 2, qc = lane & 3;
    const int r_lo = w * 16 + qr, r_hi = r_lo + 8;
    const int qc2 = qc * 2;

    unsigned bAddrLo = sbb + r_lo * 32;   // 8 words per row -> 32 B stride
    unsigned bAddrHi = sbb + r_hi * 32;

    const float fz = 0.0f;                // RZ candidate for MMA init
    float s_lo = 0.f, p_lo = 0.f, s_hi = 0.f, p_hi = 0.f;

    #pragma unroll
    for (int nb = 0; nb < 8; nb++) {
        // bits early: LDS latency hides under the MMA chain
        unsigned bl, bh;
        asm volatile("ld.shared.b32 %0, [%1];" : "=r"(bl) : "r"(bAddrLo + nb * 4));
        asm volatile("ld.shared.b32 %0, [%1];" : "=r"(bh) : "r"(bAddrHi + nb * 4));

        float acc[4][4];
        // ks = 0: init accumulators directly from MMA (C = RZ)
        {
            unsigned cb = cB_sel;
            #pragma unroll
            for (int g = 0; g < 2; g++) {
                int col = nb * 32 + g * 16 + nB;
                unsigned b0, b1, b2, b3;
                LDSM_X4(b0, b1, b2, b3, smb + B_OFF + col * 128 + ((cb ^ (col & 7)) << 4));
                MMA_BF16_INIT(acc[2 * g + 0], a[0][0], a[0][1], a[0][2], a[0][3], b0, b1, fz);
                MMA_BF16_INIT(acc[2 * g + 1], a[0][0], a[0][1], a[0][2], a[0][3], b2, b3, fz);
            }
        }
        #pragma unroll
        for (int ks = 1; ks < 4; ks++) {
            unsigned cb = 2 * ks + cB_sel;
            #pragma unroll
            for (int g = 0; g < 2; g++) {
                int col = nb * 32 + g * 16 + nB;
                unsigned b0, b1, b2, b3;
                LDSM_X4(b0, b1, b2, b3, smb + B_OFF + col * 128 + ((cb ^ (col & 7)) << 4));
                MMA_BF16(acc[2 * g + 0], a[ks][0], a[ks][1], a[ks][2], a[ks][3], b0, b1);
                MMA_BF16(acc[2 * g + 1], a[ks][0], a[ks][1], a[ks][2], a[ks][3], b2, b3);
            }
        }

        const unsigned blq = bl >> qc2, bhq = bh >> qc2;

        #pragma unroll
        for (int u = 0; u < 4; u++) {
            // MMA already produced s*EXPC (A pre-scaled): exp = ex2(acc)
            float e0 = ex2(acc[u][0]);
            float e1 = ex2(acc[u][1]);
            float e2 = ex2(acc[u][2]);
            float e3 = ex2(acc[u][3]);
            s_lo += e0 + e1;
            s_hi += e2 + e3;
            if (blq & (1u << (u * 8))) p_lo += e0;
            if (blq & (2u << (u * 8))) p_lo += e1;
            if (bhq & (1u << (u * 8))) p_hi += e2;
            if (bhq & (2u << (u * 8))) p_hi += e3;
        }
    }

    #pragma unroll
    for (int o = 1; o <= 2; o <<= 1) {
        s_lo += __shfl_xor_sync(0xffffffffu, s_lo, o);
        p_lo += __shfl_xor_sync(0xffffffffu, p_lo, o);
        s_hi += __shfl_xor_sync(0xffffffffu, s_hi, o);
        p_hi += __shfl_xor_sync(0xffffffffu, p_hi, o);
    }
    if (qc == 0) {
        atomicAdd(&g_acc[2 * mode + 0][bi * 128 + r_lo], s_lo);
        atomicAdd(&g_acc[2 * mode + 1][bi * 128 + r_lo], p_lo);
        atomicAdd(&g_acc[2 * mode + 0][bi * 128 + r_hi], s_hi);
        atomicAdd(&g_acc[2 * mode + 1][bi * 128 + r_hi], p_hi);
    }
}

// ---------------- kernel 4: finalize (single kernel, last block emits) ----------------
__global__ void finalize_kernel(float* out) {
    __shared__ double sred[128];
    int i = blockIdx.x * 128 + threadIdx.x;
    double local = 0.0;
    #pragma unroll
    for (int t = 0; t < 4; t++) {
        double A = (double)g_acc[2 * t][i];
        double B = (double)g_acc[2 * t + 1][i];
        local += log(B) - log(A + 1e-8);
    }
    sred[threadIdx.x] = local;
    __syncthreads();
    for (int o = 64; o; o >>= 1) {
        if (threadIdx.x < o) sred[threadIdx.x] += sred[threadIdx.x + o];
        __syncthreads();
    }
    if (threadIdx.x == 0) {
        atomicAdd(&g_loss, sred[0]);
        __threadfence();
        unsigned old = atomicInc(&g_cnt, 63u);            // wraps to 0 after 64th
        if (old == 63u) {
            double full = atomicAdd(&g_loss, 0.0);
            out[0] = (float)(-full / (double)Nn);
        }
    }
}

// ---------------- launch ----------------
extern "C" void kernel_launch(void* const* d_in, const int* in_sizes, int n_in,
                              void* d_out, int out_size) {
    const float* z_mp = (const float*)d_in[0];
    const float* z_sc = (const float*)d_in[1];
    const float* pos  = (const float*)d_in[2];
    float* out = (float*)d_out;

    cudaFuncSetAttribute(sim_mma_kernel,
                         cudaFuncAttributeMaxDynamicSharedMemorySize, DYN_SZ);

    normalize_kernel<<<Nn / 8, 256>>>(z_mp, 0);            // launch 0
    normalize_kernel<<<Nn / 8, 256>>>(z_sc, 1);            // launch 1
    pack_pos_kernel<<<8192, 256>>>((const float4*)pos);    // launch 2
    dim3 g(Nn / 256, Nn / 128, 4);
    sim_mma_kernel<<<g, 256, DYN_SZ>>>();                  // launch 3 <- ncu captures this
    finalize_kernel<<<64, 128>>>(out);                     // launch 4
}

// round 15
// speedup vs baseline: 1.3514x; 1.0251x over previous
#include <cuda_runtime.h>
#include <cuda_bf16.h>
#include <math.h>
#include <cstdint>

#define Nn 8192
#define Dd 64

// ---------------- device scratch ----------------
__device__ __nv_bfloat16 g_zmp_bf[Nn * Dd];    // unscaled (B side)
__device__ __nv_bfloat16 g_zsc_bf[Nn * Dd];
__device__ __nv_bfloat16 g_zmp_s[Nn * Dd];     // pre-scaled by EXPC (A side)
__device__ __nv_bfloat16 g_zsc_s[Nn * Dd];
__device__ unsigned g_bits[(size_t)Nn * Nn / 32];   // pos bitmask, 8 MB
__device__ float    g_acc[8][Nn];                   // (A,B) for 4 terms
__device__ double   g_loss;
__device__ unsigned g_cnt;

__device__ __forceinline__ unsigned smem_u32(const void* p) {
    unsigned a;
    asm("{ .reg .u64 t; cvta.to.shared.u64 t, %1; cvt.u32.u64 %0, t; }" : "=r"(a) : "l"(p));
    return a;
}
__device__ __forceinline__ float ex2(float x) {   // 2^x, 1 MUFU
    float r; asm("ex2.approx.f32 %0, %1;" : "=f"(r) : "f"(x)); return r;
}
#define EXPC 2.8853900817779268f   // 2*log2(e): exp(2v) = 2^(v*EXPC)

#define LDSM_X4(r0, r1, r2, r3, addr) \
    asm volatile("ldmatrix.sync.aligned.m8n8.x4.shared.b16 {%0,%1,%2,%3}, [%4];" \
                 : "=r"(r0), "=r"(r1), "=r"(r2), "=r"(r3) : "r"(addr))

#define MMA_BF16(c, a0, a1, a2, a3, b0, b1) \
    asm volatile("mma.sync.aligned.m16n8k16.row.col.f32.bf16.bf16.f32 " \
                 "{%0,%1,%2,%3}, {%4,%5,%6,%7}, {%8,%9}, {%0,%1,%2,%3};" \
                 : "+f"((c)[0]), "+f"((c)[1]), "+f"((c)[2]), "+f"((c)[3]) \
                 : "r"(a0), "r"(a1), "r"(a2), "r"(a3), "r"(b0), "r"(b1))

// first k-step: D = A*B + {z,z,z,z}; z==0 lets ptxas use RZ
#define MMA_BF16_INIT(c, a0, a1, a2, a3, b0, b1, z) \
    asm volatile("mma.sync.aligned.m16n8k16.row.col.f32.bf16.bf16.f32 " \
                 "{%0,%1,%2,%3}, {%4,%5,%6,%7}, {%8,%9}, {%10,%10,%10,%10};" \
                 : "=f"((c)[0]), "=f"((c)[1]), "=f"((c)[2]), "=f"((c)[3]) \
                 : "r"(a0), "r"(a1), "r"(a2), "r"(a3), "r"(b0), "r"(b1), "f"(z))

#define CP16(dst, src) \
    asm volatile("cp.async.cg.shared.global [%0], [%1], 16;" :: "r"(dst), "l"(src))
#define CP_COMMIT() asm volatile("cp.async.commit_group;" ::: "memory")
#define CP_WAIT0()  asm volatile("cp.async.wait_group 0;" ::: "memory")

// ---------------- kernel 1: row L2-normalize -> bf16 x2 (+ zero acc on first) ----------------
__global__ void normalize_kernel(const float* __restrict__ z, int which) {
    __nv_bfloat16* out  = which ? g_zsc_bf : g_zmp_bf;
    __nv_bfloat16* outs = which ? g_zsc_s  : g_zmp_s;
    if (which == 0 && blockIdx.x < 256) {
        ((float*)g_acc)[blockIdx.x * 256 + threadIdx.x] = 0.0f;
        if (blockIdx.x == 0 && threadIdx.x == 0) { g_loss = 0.0; g_cnt = 0u; }
    }
    int row  = blockIdx.x * 8 + (threadIdx.x >> 5);
    int lane = threadIdx.x & 31;
    float2 v = ((const float2*)(z + (size_t)row * Dd))[lane];
    float s = v.x * v.x + v.y * v.y;
    #pragma unroll
    for (int o = 16; o; o >>= 1) s += __shfl_xor_sync(0xffffffffu, s, o);
    float inv = 1.0f / fmaxf(sqrtf(s), 1e-12f);
    float nx = v.x * inv, ny = v.y * inv;
    ((__nv_bfloat162*)(out  + (size_t)row * Dd))[lane] = __floats2bfloat162_rn(nx, ny);
    ((__nv_bfloat162*)(outs + (size_t)row * Dd))[lane] =
        __floats2bfloat162_rn(nx * EXPC, ny * EXPC);
}

// ---------------- kernel 2: pack pos into bitmask (8 front-batched loads) ----------------
#define PK_8 (Nn * (size_t)Nn / 32)        // float4s per eighth
__global__ void pack_pos_kernel(const float4* __restrict__ pos4) {
    unsigned base = blockIdx.x * blockDim.x + threadIdx.x;
    unsigned lane = threadIdx.x & 31;
    float4 v[8];
    #pragma unroll
    for (int h = 0; h < 8; h++) v[h] = pos4[base + (size_t)h * PK_8];
    #pragma unroll
    for (int h = 0; h < 8; h++) {
        unsigned nib = (v[h].x != 0.f ? 1u : 0u) | (v[h].y != 0.f ? 2u : 0u) |
                       (v[h].z != 0.f ? 4u : 0u) | (v[h].w != 0.f ? 8u : 0u);
        unsigned word = nib << (4 * (lane & 7));
        word |= __shfl_xor_sync(0xffffffffu, word, 1);
        word |= __shfl_xor_sync(0xffffffffu, word, 2);
        word |= __shfl_xor_sync(0xffffffffu, word, 4);
        if ((lane & 7) == 0) g_bits[(base + (size_t)h * PK_8) >> 3] = word;
    }
}

// ---------------- kernel 3: HMMA similarity, 128x256 tile/CTA ----------------
// grid (32, 64, 4); mode: 0=(mp,sc) 1=(sc,mp) 2=(mp,mp) 3=(sc,sc).
// dynamic smem 56KB: A 16KB @0, B 32KB @16384, bits 8KB @49152.
#define A_OFF    0
#define B_OFF    16384
#define BITS_OFF 49152
#define DYN_SZ   57344

__global__ __launch_bounds__(256, 3) void sim_mma_kernel() {
    extern __shared__ __align__(128) unsigned char sm[];
    const unsigned smb = smem_u32(sm);
    const unsigned sbb = smb + BITS_OFF;

    const int mode = blockIdx.z;
    const __nv_bfloat16* Ap = (mode == 1 || mode == 3) ? g_zsc_s  : g_zmp_s;
    const __nv_bfloat16* Bp = (mode == 0 || mode == 3) ? g_zsc_bf : g_zmp_bf;
    const int bi = blockIdx.y, bj = blockIdx.x;       // rows bi*128, cols bj*256
    const int tid = threadIdx.x, lane = tid & 31, w = tid >> 5;

    // ---- stage tiles (swizzled) via cp.async ----
    const char* Ag = (const char*)(Ap + (size_t)bi * 128 * Dd);
    const char* Bg = (const char*)(Bp + (size_t)bj * 256 * Dd);
    #pragma unroll
    for (int i = 0; i < 4; i++) {
        int seg = i * 256 + tid;                 // A: 1024 segs of 16B
        int row = seg >> 3, c = seg & 7;
        unsigned off = row * 128 + ((c ^ (row & 7)) << 4);
        CP16(smb + A_OFF + off, Ag + row * 128 + c * 16);
    }
    #pragma unroll
    for (int i = 0; i < 8; i++) {
        int seg = i * 256 + tid;                 // B: 2048 segs of 16B
        int row = seg >> 3, c = seg & 7;
        unsigned off = row * 128 + ((c ^ (row & 7)) << 4);
        CP16(smb + B_OFF + off, Bg + row * 128 + c * 16);
    }
    {   // bits: row = tid>>1, half = tid&1  (128 rows x 8 words)
        int row = tid >> 1, half = tid & 1;
        CP16(sbb + tid * 16,
             (const char*)(g_bits + (size_t)(bi * 128 + row) * 256 + bj * 8 + half * 4));
    }
    CP_COMMIT();
    CP_WAIT0();
    __syncthreads();

    // ---- A fragments for all 4 k-steps (held in regs) ----
    const int rA = w * 16 + (lane & 15);
    const int cA_sel = lane >> 4;
    const unsigned aBase = smb + A_OFF + rA * 128;
    unsigned a[4][4];
    #pragma unroll
    for (int ks = 0; ks < 4; ks++) {
        unsigned ca = 2 * ks + cA_sel;
        LDSM_X4(a[ks][0], a[ks][1], a[ks][2], a[ks][3], aBase + ((ca ^ (rA & 7)) << 4));
    }

    const int nB = (lane & 7) + ((lane >> 4) & 1) * 8;
    const int cB_sel = (lane >> 3) & 1;
    const int qr = lane >> 2, qc = lane & 3;
    const int r_lo = w * 16 + qr, r_hi = r_lo + 8;
    const int qc2 = qc * 2;

    // B LDSM base addresses per k-step. col = nb*32 + g*16 + nB, and since
    // nb*32, g*16 are multiples of 8: col&7 == nB&7. Full address factors as
    //   bB[ks] + nb*4096 + g*2048     (the latter a compile-time immediate)
    unsigned bB[4];
    #pragma unroll
    for (int ks = 0; ks < 4; ks++) {
        unsigned cb = 2 * ks + cB_sel;
        bB[ks] = smb + B_OFF + nB * 128 + ((cb ^ (nB & 7)) << 4);
    }

    unsigned bAddrLo = sbb + r_lo * 32;   // 8 words per row -> 32 B stride
    unsigned bAddrHi = sbb + r_hi * 32;

    const float fz = 0.0f;
    float s_lo = 0.f, p_lo = 0.f, s_hi = 0.f, p_hi = 0.f;

    #pragma unroll
    for (int nb = 0; nb < 8; nb++) {
        // bits early: LDS latency hides under the MMA chain
        unsigned bl, bh;
        asm volatile("ld.shared.b32 %0, [%1];" : "=r"(bl) : "r"(bAddrLo + nb * 4));
        asm volatile("ld.shared.b32 %0, [%1];" : "=r"(bh) : "r"(bAddrHi + nb * 4));

        float acc[4][4];
        // ks = 0: init accumulators directly from MMA (C = RZ)
        #pragma unroll
        for (int g = 0; g < 2; g++) {
            unsigned b0, b1, b2, b3;
            LDSM_X4(b0, b1, b2, b3, bB[0] + nb * 4096 + g * 2048);
            MMA_BF16_INIT(acc[2 * g + 0], a[0][0], a[0][1], a[0][2], a[0][3], b0, b1, fz);
            MMA_BF16_INIT(acc[2 * g + 1], a[0][0], a[0][1], a[0][2], a[0][3], b2, b3, fz);
        }
        #pragma unroll
        for (int ks = 1; ks < 4; ks++) {
            #pragma unroll
            for (int g = 0; g < 2; g++) {
                unsigned b0, b1, b2, b3;
                LDSM_X4(b0, b1, b2, b3, bB[ks] + nb * 4096 + g * 2048);
                MMA_BF16(acc[2 * g + 0], a[ks][0], a[ks][1], a[ks][2], a[ks][3], b0, b1);
                MMA_BF16(acc[2 * g + 1], a[ks][0], a[ks][1], a[ks][2], a[ks][3], b2, b3);
            }
        }

        const unsigned blq = bl >> qc2, bhq = bh >> qc2;

        #pragma unroll
        for (int u = 0; u < 4; u++) {
            float e0 = ex2(acc[u][0]);
            float e1 = ex2(acc[u][1]);
            float e2 = ex2(acc[u][2]);
            float e3 = ex2(acc[u][3]);
            s_lo += e0 + e1;
            s_hi += e2 + e3;
            if (blq & (1u << (u * 8))) p_lo += e0;
            if (blq & (2u << (u * 8))) p_lo += e1;
            if (bhq & (1u << (u * 8))) p_hi += e2;
            if (bhq & (2u << (u * 8))) p_hi += e3;
        }
    }

    #pragma unroll
    for (int o = 1; o <= 2; o <<= 1) {
        s_lo += __shfl_xor_sync(0xffffffffu, s_lo, o);
        p_lo += __shfl_xor_sync(0xffffffffu, p_lo, o);
        s_hi += __shfl_xor_sync(0xffffffffu, s_hi, o);
        p_hi += __shfl_xor_sync(0xffffffffu, p_hi, o);
    }
    if (qc == 0) {
        atomicAdd(&g_acc[2 * mode + 0][bi * 128 + r_lo], s_lo);
        atomicAdd(&g_acc[2 * mode + 1][bi * 128 + r_lo], p_lo);
        atomicAdd(&g_acc[2 * mode + 0][bi * 128 + r_hi], s_hi);
        atomicAdd(&g_acc[2 * mode + 1][bi * 128 + r_hi], p_hi);
    }
}

// ---------------- kernel 4: finalize (single kernel, last block emits) ----------------
__global__ void finalize_kernel(float* out) {
    __shared__ double sred[128];
    int i = blockIdx.x * 128 + threadIdx.x;
    double local = 0.0;
    #pragma unroll
    for (int t = 0; t < 4; t++) {
        double A = (double)g_acc[2 * t][i];
        double B = (double)g_acc[2 * t + 1][i];
        local += log(B) - log(A + 1e-8);
    }
    sred[threadIdx.x] = local;
    __syncthreads();
    for (int o = 64; o; o >>= 1) {
        if (threadIdx.x < o) sred[threadIdx.x] += sred[threadIdx.x + o];
        __syncthreads();
    }
    if (threadIdx.x == 0) {
        atomicAdd(&g_loss, sred[0]);
        __threadfence();
        unsigned old = atomicInc(&g_cnt, 63u);            // wraps to 0 after 64th
        if (old == 63u) {
            double full = atomicAdd(&g_loss, 0.0);
            out[0] = (float)(-full / (double)Nn);
        }
    }
}

// ---------------- launch ----------------
extern "C" void kernel_launch(void* const* d_in, const int* in_sizes, int n_in,
                              void* d_out, int out_size) {
    const float* z_mp = (const float*)d_in[0];
    const float* z_sc = (const float*)d_in[1];
    const float* pos  = (const float*)d_in[2];
    float* out = (float*)d_out;

    cudaFuncSetAttribute(sim_mma_kernel,
                         cudaFuncAttributeMaxDynamicSharedMemorySize, DYN_SZ);

    normalize_kernel<<<Nn / 8, 256>>>(z_mp, 0);            // launch 0
    normalize_kernel<<<Nn / 8, 256>>>(z_sc, 1);            // launch 1
    pack_pos_kernel<<<8192, 256>>>((const float4*)pos);    // launch 2
    dim3 g(Nn / 256, Nn / 128, 4);
    sim_mma_kernel<<<g, 256, DYN_SZ>>>();                  // launch 3 <- ncu captures this
    finalize_kernel<<<64, 128>>>(out);                     // launch 4
}

// round 17
// speedup vs baseline: 1.3870x; 1.0264x over previous
#include <cuda_runtime.h>
#include <cuda_bf16.h>
#include <math.h>
#include <cstdint>

#define Nn 8192
#define Dd 64

// ---------------- device scratch ----------------
__device__ __nv_bfloat16 g_zmp_bf[Nn * Dd];    // unscaled (B side)
__device__ __nv_bfloat16 g_zsc_bf[Nn * Dd];
__device__ __nv_bfloat16 g_zmp_s[Nn * Dd];     // pre-scaled by EXPC (A side)
__device__ __nv_bfloat16 g_zsc_s[Nn * Dd];
__device__ unsigned g_bits[(size_t)Nn * Nn / 32];   // pos bitmask, 8 MB
__device__ float    g_acc[8][Nn];                   // (A,B) for 4 terms
__device__ double   g_loss;
__device__ unsigned g_cnt;

__device__ __forceinline__ unsigned smem_u32(const void* p) {
    unsigned a;
    asm("{ .reg .u64 t; cvta.to.shared.u64 t, %1; cvt.u32.u64 %0, t; }" : "=r"(a) : "l"(p));
    return a;
}
__device__ __forceinline__ float ex2(float x) {   // 2^x, 1 MUFU
    float r; asm("ex2.approx.f32 %0, %1;" : "=f"(r) : "f"(x)); return r;
}
#define EXPC 2.8853900817779268f   // 2*log2(e): exp(2v) = 2^(v*EXPC)

#define LDSM_X4(r0, r1, r2, r3, addr) \
    asm volatile("ldmatrix.sync.aligned.m8n8.x4.shared.b16 {%0,%1,%2,%3}, [%4];" \
                 : "=r"(r0), "=r"(r1), "=r"(r2), "=r"(r3) : "r"(addr))

#define MMA_BF16(c, a0, a1, a2, a3, b0, b1) \
    asm volatile("mma.sync.aligned.m16n8k16.row.col.f32.bf16.bf16.f32 " \
                 "{%0,%1,%2,%3}, {%4,%5,%6,%7}, {%8,%9}, {%0,%1,%2,%3};" \
                 : "+f"((c)[0]), "+f"((c)[1]), "+f"((c)[2]), "+f"((c)[3]) \
                 : "r"(a0), "r"(a1), "r"(a2), "r"(a3), "r"(b0), "r"(b1))

// first k-step: D = A*B + {z,z,z,z}; z==0 lets ptxas use RZ
#define MMA_BF16_INIT(c, a0, a1, a2, a3, b0, b1, z) \
    asm volatile("mma.sync.aligned.m16n8k16.row.col.f32.bf16.bf16.f32 " \
                 "{%0,%1,%2,%3}, {%4,%5,%6,%7}, {%8,%9}, {%10,%10,%10,%10};" \
                 : "=f"((c)[0]), "=f"((c)[1]), "=f"((c)[2]), "=f"((c)[3]) \
                 : "r"(a0), "r"(a1), "r"(a2), "r"(a3), "r"(b0), "r"(b1), "f"(z))

#define CP16(dst, src) \
    asm volatile("cp.async.cg.shared.global [%0], [%1], 16;" :: "r"(dst), "l"(src))
#define CP_COMMIT() asm volatile("cp.async.commit_group;" ::: "memory")
#define CP_WAIT0()  asm volatile("cp.async.wait_group 0;" ::: "memory")

// ---------------- kernel 1: row L2-normalize -> bf16 x2 (+ zero acc on first) ----------------
__global__ void normalize_kernel(const float* __restrict__ z, int which) {
    __nv_bfloat16* out  = which ? g_zsc_bf : g_zmp_bf;
    __nv_bfloat16* outs = which ? g_zsc_s  : g_zmp_s;
    if (which == 0 && blockIdx.x < 256) {
        ((float*)g_acc)[blockIdx.x * 256 + threadIdx.x] = 0.0f;
        if (blockIdx.x == 0 && threadIdx.x == 0) { g_loss = 0.0; g_cnt = 0u; }
    }
    int row  = blockIdx.x * 8 + (threadIdx.x >> 5);
    int lane = threadIdx.x & 31;
    float2 v = ((const float2*)(z + (size_t)row * Dd))[lane];
    float s = v.x * v.x + v.y * v.y;
    #pragma unroll
    for (int o = 16; o; o >>= 1) s += __shfl_xor_sync(0xffffffffu, s, o);
    float inv = 1.0f / fmaxf(sqrtf(s), 1e-12f);
    float nx = v.x * inv, ny = v.y * inv;
    ((__nv_bfloat162*)(out  + (size_t)row * Dd))[lane] = __floats2bfloat162_rn(nx, ny);
    ((__nv_bfloat162*)(outs + (size_t)row * Dd))[lane] =
        __floats2bfloat162_rn(nx * EXPC, ny * EXPC);
}

// ---------------- kernel 2: pack pos into bitmask (8 front-batched loads) ----------------
#define PK_8 (Nn * (size_t)Nn / 32)        // float4s per eighth
__global__ void pack_pos_kernel(const float4* __restrict__ pos4) {
    unsigned base = blockIdx.x * blockDim.x + threadIdx.x;
    unsigned lane = threadIdx.x & 31;
    float4 v[8];
    #pragma unroll
    for (int h = 0; h < 8; h++) v[h] = pos4[base + (size_t)h * PK_8];
    #pragma unroll
    for (int h = 0; h < 8; h++) {
        unsigned nib = (v[h].x != 0.f ? 1u : 0u) | (v[h].y != 0.f ? 2u : 0u) |
                       (v[h].z != 0.f ? 4u : 0u) | (v[h].w != 0.f ? 8u : 0u);
        unsigned word = nib << (4 * (lane & 7));
        word |= __shfl_xor_sync(0xffffffffu, word, 1);
        word |= __shfl_xor_sync(0xffffffffu, word, 2);
        word |= __shfl_xor_sync(0xffffffffu, word, 4);
        if ((lane & 7) == 0) g_bits[(base + (size_t)h * PK_8) >> 3] = word;
    }
}

// ---------------- kernel 3: HMMA similarity, 128x256 tile/CTA, 4 CTAs/SM ----------------
// grid (32, 64, 4); mode: 0=(mp,sc) 1=(sc,mp) 2=(mp,mp) 3=(sc,sc).
// dynamic smem 52KB: A 16KB @0, B 32KB @16384, bits 4KB @49152.
#define A_OFF    0
#define B_OFF    16384
#define BITS_OFF 49152
#define DYN_SZ   53248

__global__ __launch_bounds__(256, 4) void sim_mma_kernel() {
    extern __shared__ __align__(128) unsigned char sm[];
    const unsigned smb = smem_u32(sm);
    const unsigned sbb = smb + BITS_OFF;

    const int mode = blockIdx.z;
    const __nv_bfloat16* Ap = (mode == 1 || mode == 3) ? g_zsc_s  : g_zmp_s;
    const __nv_bfloat16* Bp = (mode == 0 || mode == 3) ? g_zsc_bf : g_zmp_bf;
    const int bi = blockIdx.y, bj = blockIdx.x;       // rows bi*128, cols bj*256
    const int tid = threadIdx.x, lane = tid & 31, w = tid >> 5;

    // ---- stage tiles (swizzled) via cp.async ----
    const char* Ag = (const char*)(Ap + (size_t)bi * 128 * Dd);
    const char* Bg = (const char*)(Bp + (size_t)bj * 256 * Dd);
    #pragma unroll
    for (int i = 0; i < 4; i++) {
        int seg = i * 256 + tid;                 // A: 1024 segs of 16B
        int row = seg >> 3, c = seg & 7;
        unsigned off = row * 128 + ((c ^ (row & 7)) << 4);
        CP16(smb + A_OFF + off, Ag + row * 128 + c * 16);
    }
    #pragma unroll
    for (int i = 0; i < 8; i++) {
        int seg = i * 256 + tid;                 // B: 2048 segs of 16B
        int row = seg >> 3, c = seg & 7;
        unsigned off = row * 128 + ((c ^ (row & 7)) << 4);
        CP16(smb + B_OFF + off, Bg + row * 128 + c * 16);
    }
    {   // bits: 128 rows x 8 words = 4KB; thread t -> row t>>1, half t&1
        int row = tid >> 1, half = tid & 1;
        CP16(sbb + tid * 16,
             (const char*)(g_bits + (size_t)(bi * 128 + row) * 256 + bj * 8 + half * 4));
    }
    CP_COMMIT();
    CP_WAIT0();
    __syncthreads();

    // ---- A fragments for all 4 k-steps (held in regs) ----
    const int rA = w * 16 + (lane & 15);
    const int cA_sel = lane >> 4;
    const unsigned aBase = smb + A_OFF + rA * 128;
    unsigned a[4][4];
    #pragma unroll
    for (int ks = 0; ks < 4; ks++) {
        unsigned ca = 2 * ks + cA_sel;
        LDSM_X4(a[ks][0], a[ks][1], a[ks][2], a[ks][3], aBase + ((ca ^ (rA & 7)) << 4));
    }

    const int nB = (lane & 7) + ((lane >> 4) & 1) * 8;
    const int cB_sel = (lane >> 3) & 1;
    const int qr = lane >> 2, qc = lane & 3;
    const int r_lo = w * 16 + qr, r_hi = r_lo + 8;
    const int qc2 = qc * 2;

    // B LDSM base addresses per k-step (col&7 == nB&7 since nb*32,g*16 ≡ 0 mod 8)
    unsigned bB[4];
    #pragma unroll
    for (int ks = 0; ks < 4; ks++) {
        unsigned cb = 2 * ks + cB_sel;
        bB[ks] = smb + B_OFF + nB * 128 + ((cb ^ (nB & 7)) << 4);
    }

    unsigned bAddrLo = sbb + r_lo * 32;   // 8 words per row -> 32 B stride
    unsigned bAddrHi = sbb + r_hi * 32;

    const float fz = 0.0f;
    float s_lo = 0.f, p_lo = 0.f, s_hi = 0.f, p_hi = 0.f;

    #pragma unroll
    for (int nb = 0; nb < 8; nb++) {
        // bits early: LDS latency hides under the MMA chain
        unsigned bl, bh;
        asm volatile("ld.shared.b32 %0, [%1];" : "=r"(bl) : "r"(bAddrLo + nb * 4));
        asm volatile("ld.shared.b32 %0, [%1];" : "=r"(bh) : "r"(bAddrHi + nb * 4));

        float acc[4][4];
        // ks = 0: init accumulators directly from MMA (C = RZ)
        #pragma unroll
        for (int g = 0; g < 2; g++) {
            unsigned b0, b1, b2, b3;
            LDSM_X4(b0, b1, b2, b3, bB[0] + nb * 4096 + g * 2048);
            MMA_BF16_INIT(acc[2 * g + 0], a[0][0], a[0][1], a[0][2], a[0][3], b0, b1, fz);
            MMA_BF16_INIT(acc[2 * g + 1], a[0][0], a[0][1], a[0][2], a[0][3], b2, b3, fz);
        }
        #pragma unroll
        for (int ks = 1; ks < 4; ks++) {
            #pragma unroll
            for (int g = 0; g < 2; g++) {
                unsigned b0, b1, b2, b3;
                LDSM_X4(b0, b1, b2, b3, bB[ks] + nb * 4096 + g * 2048);
                MMA_BF16(acc[2 * g + 0], a[ks][0], a[ks][1], a[ks][2], a[ks][3], b0, b1);
                MMA_BF16(acc[2 * g + 1], a[ks][0], a[ks][1], a[ks][2], a[ks][3], b2, b3);
            }
        }

        const unsigned blq = bl >> qc2, bhq = bh >> qc2;

        #pragma unroll
        for (int u = 0; u < 4; u++) {
            float e0 = ex2(acc[u][0]);
            float e1 = ex2(acc[u][1]);
            float e2 = ex2(acc[u][2]);
            float e3 = ex2(acc[u][3]);
            s_lo += e0 + e1;
            s_hi += e2 + e3;
            if (blq & (1u << (u * 8))) p_lo += e0;
            if (blq & (2u << (u * 8))) p_lo += e1;
            if (bhq & (1u << (u * 8))) p_hi += e2;
            if (bhq & (2u << (u * 8))) p_hi += e3;
        }
    }

    #pragma unroll
    for (int o = 1; o <= 2; o <<= 1) {
        s_lo += __shfl_xor_sync(0xffffffffu, s_lo, o);
        p_lo += __shfl_xor_sync(0xffffffffu, p_lo, o);
        s_hi += __shfl_xor_sync(0xffffffffu, s_hi, o);
        p_hi += __shfl_xor_sync(0xffffffffu, p_hi, o);
    }
    if (qc == 0) {
        atomicAdd(&g_acc[2 * mode + 0][bi * 128 + r_lo], s_lo);
        atomicAdd(&g_acc[2 * mode + 1][bi * 128 + r_lo], p_lo);
        atomicAdd(&g_acc[2 * mode + 0][bi * 128 + r_hi], s_hi);
        atomicAdd(&g_acc[2 * mode + 1][bi * 128 + r_hi], p_hi);
    }
}

// ---------------- kernel 4: finalize (single kernel, last block emits) ----------------
__global__ void finalize_kernel(float* out) {
    __shared__ double sred[128];
    int i = blockIdx.x * 128 + threadIdx.x;
    double local = 0.0;
    #pragma unroll
    for (int t = 0; t < 4; t++) {
        double A = (double)g_acc[2 * t][i];
        double B = (double)g_acc[2 * t + 1][i];
        local += log(B) - log(A + 1e-8);
    }
    sred[threadIdx.x] = local;
    __syncthreads();
    for (int o = 64; o; o >>= 1) {
        if (threadIdx.x < o) sred[threadIdx.x] += sred[threadIdx.x + o];
        __syncthreads();
    }
    if (threadIdx.x == 0) {
        atomicAdd(&g_loss, sred[0]);
        __threadfence();
        unsigned old = atomicInc(&g_cnt, 63u);            // wraps to 0 after 64th
        if (old == 63u) {
            double full = atomicAdd(&g_loss, 0.0);
            out[0] = (float)(-full / (double)Nn);
        }
    }
}

// ---------------- launch ----------------
extern "C" void kernel_launch(void* const* d_in, const int* in_sizes, int n_in,
                              void* d_out, int out_size) {
    const float* z_mp = (const float*)d_in[0];
    const float* z_sc = (const float*)d_in[1];
    const float* pos  = (const float*)d_in[2];
    float* out = (float*)d_out;

    cudaFuncSetAttribute(sim_mma_kernel,
                         cudaFuncAttributeMaxDynamicSharedMemorySize, DYN_SZ);

    normalize_kernel<<<Nn / 8, 256>>>(z_mp, 0);            // launch 0
    normalize_kernel<<<Nn / 8, 256>>>(z_sc, 1);            // launch 1
    pack_pos_kernel<<<8192, 256>>>((const float4*)pos);    // launch 2
    dim3 g(Nn / 256, Nn / 128, 4);
    sim_mma_kernel<<<g, 256, DYN_SZ>>>();                  // launch 3 <- ncu captures this
    finalize_kernel<<<64, 128>>>(out);                     // launch 4
}